// round 16
// baseline (speedup 1.0000x reference)
#include <cuda_runtime.h>
#include <cuda_fp16.h>
#include <math.h>
#include <stdint.h>

// ---------------- problem constants ----------------
#define FNUM  16
#define CCH   320
#define HWN   1024
#define BFN   32            // B*F
#define MTOK  32768         // BFN*HWN
#define NHEAD 8
#define DHEAD 40
#define NGRP  32
#define CPG   10
#define INNER 1280

// ---------------- scratch ----------------
__device__ __half g_hs [(size_t)MTOK * CCH];
__device__ __half g_q  [(size_t)MTOK * CCH];
__device__ __half g_k  [(size_t)MTOK * CCH];
__device__ __half g_v  [(size_t)MTOK * CCH];
__device__ __half g_tok[(size_t)MTOK * CCH];
__device__ __half g_o  [(size_t)MTOK * CCH];
__device__ __half g_g  [(size_t)MTOK * INNER];
#define W_PIN   0
#define W_QKV0  102400
#define W_O0    409600
#define W_QKV1  512000
#define W_O1    819200
#define W_FF1   921600
#define W_FF2   1740800
#define W_POUT  2150400
#define W_COMB  2252800
#define WTOT    2662400
__device__ __half g_wh[WTOT];
__device__ float g_pe [FNUM * CCH];
__device__ float g_gnm[BFN * NGRP];
__device__ float g_gnr[BFN * NGRP];
__device__ float g_bc [CCH];

// ================= helpers =================
__device__ __forceinline__ void ldsm4(uint32_t* r, const void* p) {
    uint32_t a = (uint32_t)__cvta_generic_to_shared(p);
    asm volatile("ldmatrix.sync.aligned.m8n8.x4.shared.b16 {%0,%1,%2,%3}, [%4];"
        : "=r"(r[0]), "=r"(r[1]), "=r"(r[2]), "=r"(r[3]) : "r"(a));
}
__device__ __forceinline__ void ldsm4t(uint32_t* r, const void* p) {
    uint32_t a = (uint32_t)__cvta_generic_to_shared(p);
    asm volatile("ldmatrix.sync.aligned.m8n8.x4.trans.shared.b16 {%0,%1,%2,%3}, [%4];"
        : "=r"(r[0]), "=r"(r[1]), "=r"(r[2]), "=r"(r[3]) : "r"(a));
}
__device__ __forceinline__ void mma16816(float* d, const uint32_t* a, const uint32_t* b) {
    asm volatile("mma.sync.aligned.m16n8k16.row.col.f32.f16.f16.f32 "
        "{%0,%1,%2,%3}, {%4,%5,%6,%7}, {%8,%9}, {%0,%1,%2,%3};"
        : "+f"(d[0]), "+f"(d[1]), "+f"(d[2]), "+f"(d[3])
        : "r"(a[0]), "r"(a[1]), "r"(a[2]), "r"(a[3]), "r"(b[0]), "r"(b[1]));
}
__device__ __forceinline__ void cpa16(void* dst, const void* src) {
    uint32_t d = (uint32_t)__cvta_generic_to_shared(dst);
    asm volatile("cp.async.cg.shared.global [%0], [%1], 16;" :: "r"(d), "l"(src));
}
#define CP_COMMIT() asm volatile("cp.async.commit_group;" ::: "memory")
#define CP_WAIT2()  asm volatile("cp.async.wait_group 2;" ::: "memory")

__device__ __forceinline__ uint32_t pack_h2(float t0, float t1) {
    __half h0 = __float2half_rn(t0), h1 = __float2half_rn(t1);
    return (uint32_t)__half_as_ushort(h0) | ((uint32_t)__half_as_ushort(h1) << 16);
}

// ================= single-pass fp16 GEMM, 4-stage cp.async pipeline =========
// MODE 0: Hs[m,n] = fp16(v + bias)
// MODE 1: Hs[perm(m),n] += v + bias      (fp16 RMW)
// MODE 2: out[(bf*CCH+n)*HWN+hw] = v + bias + X   (smem-transposed, coalesced)
// MODE 4: QKV n-split -> Hs/Hk/Hv (fp16)
// MODE 6: split-K fused final: A = [Ag(K1=320) | Ag2(K2=1280)], B = [Bg | Bg2],
//         epilogue = MODE 2
#define APAD 40
#define BPAD 72
#define SM_A_STG 10240            // 128 rows * 80B
#define SM_B_STG 4608             // 32 rows * 144B
#define SM_A(s) ((s) * SM_A_STG)
#define SM_B(s) (40960 + (s) * SM_B_STG)
#define SM_TOTAL 59392
#define TRP 132                   // MODE2 transpose pitch (floats)

template <int MODE>
__global__ __launch_bounds__(256, 3) void bgemm_kernel(
    const __half* __restrict__ Ag, const __half* __restrict__ Bg,
    const __half* __restrict__ Ag2, const __half* __restrict__ Bg2,
    const float* __restrict__ bias, float* __restrict__ C,
    const float* __restrict__ X,
    __half* __restrict__ Hs, __half* __restrict__ Hk, __half* __restrict__ Hv,
    int M, int N, int K)
{
    extern __shared__ char sm[];
    const int tid  = threadIdx.x;
    const int lane = tid & 31;
    const int wm   = (tid >> 5) & 3;
    const int wn   = tid >> 7;
    const int m0   = blockIdx.y * 128;
    const int n0   = blockIdx.x * 64;

    const int mbase = wm * 32;
    const int nbase = wn * 32;
    const int lrow  = lane & 15;
    const int lcol8 = (lane >> 4) * 8;

    float acc[2][4][4];
    #pragma unroll
    for (int a = 0; a < 2; a++)
        #pragma unroll
        for (int b = 0; b < 4; b++)
            #pragma unroll
            for (int c = 0; c < 4; c++) acc[a][b][c] = 0.f;

    const int arow0 = tid >> 1;
    const int ac0   = (tid & 1) * 2;
    const int brow  = tid >> 3;
    const int bch   = tid & 7;

    auto load_stage = [&](int s, int kt) {
        const __half* Asrc = Ag;
        const __half* Bsrc = Bg;
        size_t astr = (size_t)K;
        int kk = kt;
        if (MODE == 6) {
            if (kt < CCH) { astr = CCH; }
            else { Asrc = Ag2; Bsrc = Bg2; astr = INNER; kk = kt - CCH; }
        }
        #pragma unroll
        for (int i = 0; i < 2; i++) {
            int c = ac0 + i;
            cpa16(sm + SM_A(s) + arow0 * 80 + c * 16,
                  Asrc + (size_t)(m0 + arow0) * astr + kk + c * 8);
        }
        cpa16(sm + SM_B(s) + brow * 144 + bch * 16,
              Bsrc + (size_t)(kk + brow) * N + n0 + bch * 8);
    };

    const int ntile = K >> 5;
    load_stage(0, 0);  CP_COMMIT();
    load_stage(1, 32); CP_COMMIT();
    load_stage(2, 64); CP_COMMIT();

    for (int t = 0; t < ntile; t++) {
        CP_WAIT2();
        __syncthreads();
        if (t + 3 < ntile) load_stage((t + 3) & 3, (t + 3) * 32);
        CP_COMMIT();

        const int s = t & 3;
        const __half (*As)[APAD] = (const __half(*)[APAD])(sm + SM_A(s));
        const __half (*Bs)[BPAD] = (const __half(*)[BPAD])(sm + SM_B(s));

        #pragma unroll
        for (int ks = 0; ks < 2; ks++) {
            uint32_t ah[2][4], bh[4][2];
            #pragma unroll
            for (int mi = 0; mi < 2; mi++)
                ldsm4(ah[mi], &As[mbase + mi * 16 + lrow][ks * 16 + lcol8]);
            #pragma unroll
            for (int nj = 0; nj < 2; nj++) {
                uint32_t tmp[4];
                ldsm4t(tmp, &Bs[ks * 16 + lrow][nbase + nj * 16 + lcol8]);
                bh[nj * 2][0] = tmp[0]; bh[nj * 2][1] = tmp[1];
                bh[nj * 2 + 1][0] = tmp[2]; bh[nj * 2 + 1][1] = tmp[3];
            }
            #pragma unroll
            for (int mi = 0; mi < 2; mi++)
                #pragma unroll
                for (int ni = 0; ni < 4; ni++)
                    mma16816(acc[mi][ni], ah[mi], bh[ni]);
        }
    }

    // ---- epilogue ----
    const int erow = lane >> 2;
    const int ecol = (lane & 3) * 2;

    if (MODE == 2 || MODE == 6) {
        __syncthreads();
        float* tr = (float*)sm;   // 64 * TRP floats = 33792 B < SM_TOTAL
        #pragma unroll
        for (int mi = 0; mi < 2; mi++) {
            #pragma unroll
            for (int rr = 0; rr < 2; rr++) {
                const int ml = mbase + mi * 16 + rr * 8 + erow;
                #pragma unroll
                for (int ni = 0; ni < 4; ni++) {
                    const int nl = nbase + ni * 8 + ecol;
                    tr[nl * TRP + ml]       = acc[mi][ni][rr * 2 + 0] + bias[n0 + nl];
                    tr[(nl + 1) * TRP + ml] = acc[mi][ni][rr * 2 + 1] + bias[n0 + nl + 1];
                }
            }
        }
        __syncthreads();
        const int bfi = m0 >> 10, hw0 = m0 & 1023;
        const int warp = tid >> 5;
        #pragma unroll
        for (int r8 = 0; r8 < 8; r8++) {
            const int n = warp + r8 * 8;
            size_t off = ((size_t)(bfi * CCH + n0 + n)) * HWN + hw0 + lane * 4;
            float4 xv = *(const float4*)(X + off);
            const float* tp = tr + n * TRP + lane * 4;
            float4 w;
            w.x = tp[0] + xv.x;
            w.y = tp[1] + xv.y;
            w.z = tp[2] + xv.z;
            w.w = tp[3] + xv.w;
            *(float4*)(C + off) = w;
        }
        return;
    }

    const int seg4 = (n0 + nbase) / CCH;   // MODE 4: constant per warp
    #pragma unroll
    for (int mi = 0; mi < 2; mi++) {
        #pragma unroll
        for (int rr = 0; rr < 2; rr++) {
            const int m = m0 + mbase + mi * 16 + rr * 8 + erow;
            int mrow = m;
            if (MODE == 1) {
                int f = m & 15, nd = m >> 4;
                mrow = (((nd >> 10) * FNUM + f) << 10) + (nd & 1023);
            }
            #pragma unroll
            for (int ni = 0; ni < 4; ni++) {
                const int n = n0 + nbase + ni * 8 + ecol;
                float v0 = acc[mi][ni][rr * 2 + 0];
                float v1 = acc[mi][ni][rr * 2 + 1];
                if (bias) { v0 += bias[n]; v1 += bias[n + 1]; }
                if (MODE == 0) {
                    *(uint32_t*)(Hs + (size_t)mrow * N + n) = pack_h2(v0, v1);
                } else if (MODE == 1) {
                    uint32_t* p = (uint32_t*)(Hs + (size_t)mrow * N + n);
                    float2 old = __half22float2(*(const __half2*)p);
                    *p = pack_h2(old.x + v0, old.y + v1);
                } else { // MODE 4
                    __half* dst = (seg4 == 0) ? Hs : (seg4 == 1) ? Hk : Hv;
                    *(uint32_t*)(dst + (size_t)m * CCH + (n - seg4 * CCH)) = pack_h2(v0, v1);
                }
            }
        }
    }
}

// ================= FF1+GEGLU: 128x128 tile, 4-stage, interleaved weights ====
#define BW_PITCH 136              // halves per B row (272 B)
#define SMW_A_STG 10240
#define SMW_B_STG 8704            // 32 * 272B
#define SMW_A(s) ((s) * SMW_A_STG)
#define SMW_B(s) (40960 + (s) * SMW_B_STG)
#define SMW_TOTAL 75776

__global__ __launch_bounds__(256, 2) void ff1_kernel(
    const __half* __restrict__ Ag, const __half* __restrict__ Bg,
    const float* __restrict__ bias, __half* __restrict__ O, int M, int N, int K)
{
    extern __shared__ char sm[];
    const int tid  = threadIdx.x;
    const int lane = tid & 31;
    const int wm   = (tid >> 5) & 3;
    const int wn   = tid >> 7;
    const int m0   = blockIdx.y * 128;
    const int n0   = blockIdx.x * 128;

    const int mbase = wm * 32;
    const int nbase = wn * 64;
    const int lrow  = lane & 15;
    const int lcol8 = (lane >> 4) * 8;

    float acc[2][8][4];
    #pragma unroll
    for (int a = 0; a < 2; a++)
        #pragma unroll
        for (int b = 0; b < 8; b++)
            #pragma unroll
            for (int c = 0; c < 4; c++) acc[a][b][c] = 0.f;

    const int arow0 = tid >> 1;
    const int ac0   = (tid & 1) * 2;
    const int brow  = tid >> 3;
    const int bch   = tid & 7;

    auto load_stage = [&](int s, int kt) {
        #pragma unroll
        for (int i = 0; i < 2; i++) {
            int c = ac0 + i;
            cpa16(sm + SMW_A(s) + arow0 * 80 + c * 16,
                  Ag + (size_t)(m0 + arow0) * K + kt + c * 8);
        }
        #pragma unroll
        for (int i = 0; i < 2; i++) {
            cpa16(sm + SMW_B(s) + brow * 272 + (bch + i * 8) * 16,
                  Bg + (size_t)(kt + brow) * N + n0 + bch * 8 + i * 64);
        }
    };

    const int ntile = K >> 5;
    load_stage(0, 0);  CP_COMMIT();
    load_stage(1, 32); CP_COMMIT();
    load_stage(2, 64); CP_COMMIT();

    for (int t = 0; t < ntile; t++) {
        CP_WAIT2();
        __syncthreads();
        if (t + 3 < ntile) load_stage((t + 3) & 3, (t + 3) * 32);
        CP_COMMIT();

        const int s = t & 3;
        const __half (*As)[APAD] = (const __half(*)[APAD])(sm + SMW_A(s));
        const __half (*Bs)[BW_PITCH] = (const __half(*)[BW_PITCH])(sm + SMW_B(s));

        #pragma unroll
        for (int ks = 0; ks < 2; ks++) {
            uint32_t ah[2][4], bh[8][2];
            #pragma unroll
            for (int mi = 0; mi < 2; mi++)
                ldsm4(ah[mi], &As[mbase + mi * 16 + lrow][ks * 16 + lcol8]);
            #pragma unroll
            for (int nj = 0; nj < 4; nj++) {
                uint32_t tmp[4];
                ldsm4t(tmp, &Bs[ks * 16 + lrow][nbase + nj * 16 + lcol8]);
                bh[nj * 2][0] = tmp[0]; bh[nj * 2][1] = tmp[1];
                bh[nj * 2 + 1][0] = tmp[2]; bh[nj * 2 + 1][1] = tmp[3];
            }
            #pragma unroll
            for (int mi = 0; mi < 2; mi++)
                #pragma unroll
                for (int ni = 0; ni < 8; ni++)
                    mma16816(acc[mi][ni], ah[mi], bh[ni]);
        }
    }

    // ---- epilogue: GEGLU on interleaved (a,g) 16-col pairs ----
    const int erow = lane >> 2;
    const int ecol = (lane & 3) * 2;
    #pragma unroll
    for (int mi = 0; mi < 2; mi++) {
        #pragma unroll
        for (int rr = 0; rr < 2; rr++) {
            const int m = m0 + mbase + mi * 16 + rr * 8 + erow;
            #pragma unroll
            for (int p = 0; p < 4; p++) {
                const int tile16 = (n0 + nbase + p * 16) >> 4;
                const int acol = tile16 * 8 + ecol;
                float a0 = acc[mi][2 * p][rr * 2 + 0] + bias[acol];
                float a1 = acc[mi][2 * p][rr * 2 + 1] + bias[acol + 1];
                float g0 = acc[mi][2 * p + 1][rr * 2 + 0] + bias[INNER + acol];
                float g1 = acc[mi][2 * p + 1][rr * 2 + 1] + bias[INNER + acol + 1];
                float r0 = a0 * (0.5f * g0 * (1.f + erff(g0 * 0.7071067811865476f)));
                float r1 = a1 * (0.5f * g1 * (1.f + erff(g1 * 0.7071067811865476f)));
                *(uint32_t*)(O + (size_t)m * INNER + acol) = pack_h2(r0, r1);
            }
        }
    }
}

// ---------------- batched weight fp32 -> fp16 --------------------------------
struct WSegs {
    const float* src[12];
    int off[12], rows[12], cols[12], pitch[12], coloff[12], ilv[12], blk0[12];
};
__global__ __launch_bounds__(256) void convw_all(WSegs T, __half* __restrict__ dh)
{
    int b = blockIdx.x;
    int s = 0;
    #pragma unroll
    for (int i = 1; i < 12; i++) if (b >= T.blk0[i]) s = i;
    int idx = (b - T.blk0[s]) * 256 + threadIdx.x;
    int cols = T.cols[s];
    if (idx >= T.rows[s] * cols) return;
    int r = idx / cols, c = idx % cols;
    float v = T.src[s][idx];
    int nc;
    if (T.ilv[s]) {
        int half = cols >> 1;
        if (c < half) nc = (c >> 3) * 16 + (c & 7);
        else { int c2 = c - half; nc = (c2 >> 3) * 16 + 8 + (c2 & 7); }
    } else {
        nc = T.coloff[s] + c;
    }
    dh[(size_t)T.off[s] + (size_t)r * T.pitch[s] + nc] = __float2half_rn(v);
}

// ---------------- combined bias: bc = b2 @ Wp + bp ---------------------------
__global__ void bias_comb_kernel(const float* __restrict__ b2, const float* __restrict__ wp,
                                 const float* __restrict__ bp, float* __restrict__ bc)
{
    int n = threadIdx.x;
    float s = bp[n];
    for (int k = 0; k < CCH; k++) s += b2[k] * wp[k * CCH + n];
    bc[n] = s;
}

// ---------------- PE ----------------
__global__ void pe_kernel(float* __restrict__ pe)
{
    int p = blockIdx.x;
    int i = threadIdx.x;
    double div = exp((double)(2 * i) * (-log(10000.0) / (double)CCH));
    double a = (double)p * div;
    pe[p * CCH + 2 * i]     = (float)sin(a);
    pe[p * CCH + 2 * i + 1] = (float)cos(a);
}

// ---------------- GroupNorm stats ----------------
__global__ __launch_bounds__(256) void gn_stats_kernel(
    const float* __restrict__ x, float* __restrict__ mean, float* __restrict__ rstd)
{
    int bg = blockIdx.x;
    int bf = bg >> 5, g = bg & 31;
    const float* p = x + ((size_t)bf * CCH + g * CPG) * HWN;
    float s = 0.f, q = 0.f;
    for (int idx = threadIdx.x; idx < CPG * HWN; idx += 256) {
        float v = p[idx];
        s += v; q += v * v;
    }
    #pragma unroll
    for (int o = 16; o > 0; o >>= 1) {
        s += __shfl_xor_sync(0xffffffffu, s, o);
        q += __shfl_xor_sync(0xffffffffu, q, o);
    }
    __shared__ float ss[8], qq[8];
    int warp = threadIdx.x >> 5, lane = threadIdx.x & 31;
    if (lane == 0) { ss[warp] = s; qq[warp] = q; }
    __syncthreads();
    if (threadIdx.x == 0) {
        float S = 0.f, Q = 0.f;
        #pragma unroll
        for (int i = 0; i < 8; i++) { S += ss[i]; Q += qq[i]; }
        float m = S / (float)(CPG * HWN);
        float var = Q / (float)(CPG * HWN) - m * m;
        mean[bg] = m;
        rstd[bg] = rsqrtf(var + 1e-6f);
    }
}

// ---------------- GroupNorm apply + transpose -> fp16 tokens ----------------
__global__ void gn_tok_kernel(
    const float* __restrict__ x, const float* __restrict__ gw, const float* __restrict__ gb,
    const float* __restrict__ mean, const float* __restrict__ rstd,
    __half* __restrict__ th)
{
    __shared__ float tile[32][33];
    int bf = blockIdx.z;
    int c0 = blockIdx.y * 32;
    int hw0 = blockIdx.x * 32;
    #pragma unroll
    for (int j = 0; j < 4; j++) {
        int c = c0 + threadIdx.y + j * 8;
        float v = x[((size_t)bf * CCH + c) * HWN + hw0 + threadIdx.x];
        int bg = bf * NGRP + c / CPG;
        v = (v - mean[bg]) * rstd[bg] * gw[c] + gb[c];
        tile[threadIdx.y + j * 8][threadIdx.x] = v;
    }
    __syncthreads();
    #pragma unroll
    for (int j = 0; j < 4; j++) {
        int hw = hw0 + threadIdx.y + j * 8;
        float v = tile[threadIdx.x][threadIdx.y + j * 8];
        th[((size_t)bf * HWN + hw) * CCH + c0 + threadIdx.x] = __float2half_rn(v);
    }
}

// ---------------- LayerNorm (warp per row, fp16 in/out) ----------------
__global__ __launch_bounds__(256) void ln_kernel(
    const __half* __restrict__ in, const float* __restrict__ w, const float* __restrict__ bvec,
    const float* __restrict__ pe, __half* __restrict__ oh, int temporal)
{
    const int warp = threadIdx.x >> 5, lane = threadIdx.x & 31;
    const int r = blockIdx.x * 8 + warp;
    int src = r, f = 0;
    if (temporal) {
        f = r & 15;
        int nd = r >> 4;
        src = (((nd >> 10) * FNUM + f) << 10) + (nd & 1023);
    }
    const __half2* row2 = (const __half2*)(in + (size_t)src * CCH);
    float2 vv[5];
    float s = 0.f, q = 0.f;
    #pragma unroll
    for (int i = 0; i < 5; i++) {
        float2 v = __half22float2(row2[lane + i * 32]);
        vv[i] = v;
        s += v.x + v.y;
        q += v.x * v.x + v.y * v.y;
    }
    #pragma unroll
    for (int o = 16; o > 0; o >>= 1) {
        s += __shfl_xor_sync(0xffffffffu, s, o);
        q += __shfl_xor_sync(0xffffffffu, q, o);
    }
    const float m = s / (float)CCH;
    const float rs = rsqrtf(q / (float)CCH - m * m + 1e-5f);
    uint32_t* orow = (uint32_t*)(oh + (size_t)r * CCH);
    #pragma unroll
    for (int i = 0; i < 5; i++) {
        int c = (lane + i * 32) * 2;
        float o0 = (vv[i].x - m) * rs * w[c] + bvec[c];
        float o1 = (vv[i].y - m) * rs * w[c + 1] + bvec[c + 1];
        if (temporal) { o0 += pe[f * CCH + c]; o1 += pe[f * CCH + c + 1]; }
        orow[lane + i * 32] = pack_h2(o0, o1);
    }
}

// ---------------- temporal attention (block per token-group n, fp16 I/O) ----
#define ATT_PITCH 321
#define ATT_SMEM ((3 * 16 * ATT_PITCH + 8 * 16 * 16) * 4)
__global__ __launch_bounds__(256) void attn_kernel(
    const __half* __restrict__ Q, const __half* __restrict__ K,
    const __half* __restrict__ V, __half* __restrict__ Oh)
{
    extern __shared__ float smf[];
    float* qs = smf;
    float* ks = smf + 16 * ATT_PITCH;
    float* vs = smf + 2 * 16 * ATT_PITCH;
    float* sc = smf + 3 * 16 * ATT_PITCH;   // [8][16][16]
    const int tid = threadIdx.x;
    const size_t base = (size_t)blockIdx.x * FNUM * CCH;

    #pragma unroll
    for (int i = 0; i < 10; i++) {
        int idx2 = tid + i * 256;
        int row = idx2 / 160;
        int c2 = (idx2 % 160) * 2;
        float2 a = __half22float2(*(const __half2*)(Q + base + row * CCH + c2));
        qs[row * ATT_PITCH + c2] = a.x; qs[row * ATT_PITCH + c2 + 1] = a.y;
        float2 b = __half22float2(*(const __half2*)(K + base + row * CCH + c2));
        ks[row * ATT_PITCH + c2] = b.x; ks[row * ATT_PITCH + c2 + 1] = b.y;
        float2 c = __half22float2(*(const __half2*)(V + base + row * CCH + c2));
        vs[row * ATT_PITCH + c2] = c.x; vs[row * ATT_PITCH + c2 + 1] = c.y;
    }
    __syncthreads();

    {
        const int qf = tid >> 4, kf = tid & 15;
        const float* qp = qs + qf * ATT_PITCH;
        const float* kp = ks + kf * ATT_PITCH;
        #pragma unroll
        for (int h = 0; h < 8; h++) {
            float s = 0.f;
            #pragma unroll
            for (int j = 0; j < DHEAD; j++) s = fmaf(qp[h * DHEAD + j], kp[h * DHEAD + j], s);
            sc[h * 256 + qf * 16 + kf] = s * 0.15811388300841897f;
        }
    }
    __syncthreads();

    if (tid < 128) {
        float* row = sc + (tid >> 4) * 256 + (tid & 15) * 16;
        float m = -1e30f;
        #pragma unroll
        for (int k2 = 0; k2 < 16; k2++) m = fmaxf(m, row[k2]);
        float sum = 0.f;
        #pragma unroll
        for (int k2 = 0; k2 < 16; k2++) {
            float e = expf(row[k2] - m);
            row[k2] = e;
            sum += e;
        }
        float inv = 1.f / sum;
        #pragma unroll
        for (int k2 = 0; k2 < 16; k2++) row[k2] *= inv;
    }
    __syncthreads();

    #pragma unroll
    for (int i = 0; i < 20; i++) {
        int idx = tid + i * 256;
        int f = idx / CCH, c = idx % CCH;
        int h = c / DHEAD;
        const float* pr = sc + h * 256 + f * 16;
        float o = 0.f;
        #pragma unroll
        for (int k2 = 0; k2 < 16; k2++) o = fmaf(pr[k2], vs[k2 * ATT_PITCH + c], o);
        Oh[base + (size_t)f * CCH + c] = __float2half_rn(o);
    }
}

// ---------------- host orchestration ----------------
extern "C" void kernel_launch(void* const* d_in, const int* in_sizes, int n_in,
                              void* d_out, int out_size)
{
    const float* x      = (const float*)d_in[0];
    const float* gn_w   = (const float*)d_in[1];
    const float* gn_b   = (const float*)d_in[2];
    const float* pin_w  = (const float*)d_in[3];
    const float* pin_b  = (const float*)d_in[4];
    const float* lnw[2]  = { (const float*)d_in[5],  (const float*)d_in[12] };
    const float* lnb[2]  = { (const float*)d_in[6],  (const float*)d_in[13] };
    const float* wq[2]   = { (const float*)d_in[7],  (const float*)d_in[14] };
    const float* wk[2]   = { (const float*)d_in[8],  (const float*)d_in[15] };
    const float* wv[2]   = { (const float*)d_in[9],  (const float*)d_in[16] };
    const float* wo[2]   = { (const float*)d_in[10], (const float*)d_in[17] };
    const float* bo[2]   = { (const float*)d_in[11], (const float*)d_in[18] };
    const float* ffln_w = (const float*)d_in[19];
    const float* ffln_b = (const float*)d_in[20];
    const float* ff_w1  = (const float*)d_in[21];
    const float* ff_b1  = (const float*)d_in[22];
    const float* ff_w2  = (const float*)d_in[23];
    const float* ff_b2  = (const float*)d_in[24];
    const float* pout_w = (const float*)d_in[25];
    const float* pout_b = (const float*)d_in[26];
    float* out = (float*)d_out;

    float *pe, *gnm, *gnr, *bc;
    __half *hs, *q, *k, *v, *tok, *o, *g, *wh;
    cudaGetSymbolAddress((void**)&hs,  g_hs);
    cudaGetSymbolAddress((void**)&q,   g_q);
    cudaGetSymbolAddress((void**)&k,   g_k);
    cudaGetSymbolAddress((void**)&v,   g_v);
    cudaGetSymbolAddress((void**)&pe,  g_pe);
    cudaGetSymbolAddress((void**)&gnm, g_gnm);
    cudaGetSymbolAddress((void**)&gnr, g_gnr);
    cudaGetSymbolAddress((void**)&tok, g_tok);
    cudaGetSymbolAddress((void**)&o,   g_o);
    cudaGetSymbolAddress((void**)&g,   g_g);
    cudaGetSymbolAddress((void**)&wh,  g_wh);
    cudaGetSymbolAddress((void**)&bc,  g_bc);

    cudaFuncSetAttribute(bgemm_kernel<0>, cudaFuncAttributeMaxDynamicSharedMemorySize, SM_TOTAL);
    cudaFuncSetAttribute(bgemm_kernel<1>, cudaFuncAttributeMaxDynamicSharedMemorySize, SM_TOTAL);
    cudaFuncSetAttribute(bgemm_kernel<4>, cudaFuncAttributeMaxDynamicSharedMemorySize, SM_TOTAL);
    cudaFuncSetAttribute(bgemm_kernel<6>, cudaFuncAttributeMaxDynamicSharedMemorySize, SM_TOTAL);
    cudaFuncSetAttribute(ff1_kernel, cudaFuncAttributeMaxDynamicSharedMemorySize, SMW_TOTAL);
    cudaFuncSetAttribute(attn_kernel, cudaFuncAttributeMaxDynamicSharedMemorySize, ATT_SMEM);

    dim3 gN320(5, 256);
    dim3 gQKV(15, 256);
    dim3 gFF1(20, 256);

    pe_kernel<<<FNUM, CCH / 2>>>(pe);
    gn_stats_kernel<<<BFN * NGRP, 256>>>(x, gnm, gnr);
    gn_tok_kernel<<<dim3(HWN / 32, CCH / 32, BFN), dim3(32, 8)>>>(x, gn_w, gn_b, gnm, gnr, tok);

    // single batched weight conversion
    {
        WSegs T;
        const float* srcs[12] = { pin_w, wq[0], wk[0], wv[0], wo[0],
                                  wq[1], wk[1], wv[1], wo[1], ff_w1, ff_w2, pout_w };
        int offs[12]  = { W_PIN, W_QKV0, W_QKV0, W_QKV0, W_O0,
                          W_QKV1, W_QKV1, W_QKV1, W_O1, W_FF1, W_FF2, W_POUT };
        int rows[12]  = { 320, 320, 320, 320, 320, 320, 320, 320, 320, 320, 1280, 320 };
        int cols[12]  = { 320, 320, 320, 320, 320, 320, 320, 320, 320, 2560, 320, 320 };
        int pitch[12] = { 320, 960, 960, 960, 320, 960, 960, 960, 320, 2560, 320, 320 };
        int colo[12]  = { 0, 0, 320, 640, 0, 0, 320, 640, 0, 0, 0, 0 };
        int ilv[12]   = { 0, 0, 0, 0, 0, 0, 0, 0, 0, 1, 0, 0 };
        int blk = 0;
        for (int i = 0; i < 12; i++) {
            T.src[i] = srcs[i]; T.off[i] = offs[i]; T.rows[i] = rows[i]; T.cols[i] = cols[i];
            T.pitch[i] = pitch[i]; T.coloff[i] = colo[i]; T.ilv[i] = ilv[i];
            T.blk0[i] = blk;
            blk += (rows[i] * cols[i] + 255) / 256;
        }
        convw_all<<<blk, 256>>>(T, wh);
    }
    // Wcomb = W2 @ Wp (fp16, into weight pool); combined bias bc = b2@Wp + bp
    bgemm_kernel<0><<<dim3(5, 10), 256, SM_TOTAL>>>(wh + W_FF2, wh + W_POUT,
        nullptr, nullptr, nullptr, nullptr, nullptr, wh + W_COMB, nullptr, nullptr,
        INNER, CCH, CCH);
    bias_comb_kernel<<<1, CCH>>>(ff_b2, pout_w, pout_b, bc);

    // proj_in -> hs (fp16)
    bgemm_kernel<0><<<gN320, 256, SM_TOTAL>>>(tok, wh + W_PIN,
        nullptr, nullptr, pin_b, nullptr, nullptr, hs, nullptr, nullptr, MTOK, CCH, CCH);

    const int WQKV[2] = { W_QKV0, W_QKV1 };
    const int WO[2]   = { W_O0, W_O1 };
    for (int i = 0; i < 2; i++) {
        ln_kernel<<<MTOK / 8, 256>>>(hs, lnw[i], lnb[i], pe, tok, 1);
        bgemm_kernel<4><<<gQKV, 256, SM_TOTAL>>>(tok, wh + WQKV[i],
            nullptr, nullptr, nullptr, nullptr, nullptr, q, k, v, MTOK, 960, CCH);
        attn_kernel<<<2048, 256, ATT_SMEM>>>(q, k, v, o);
        bgemm_kernel<1><<<gN320, 256, SM_TOTAL>>>(o, wh + WO[i],
            nullptr, nullptr, bo[i], nullptr, nullptr, hs, nullptr, nullptr, MTOK, CCH, CCH);
    }

    ln_kernel<<<MTOK / 8, 256>>>(hs, ffln_w, ffln_b, pe, tok, 0);
    // FF1 + GEGLU fused (interleaved weights, 128x128 tiles) -> g
    ff1_kernel<<<gFF1, 256, SMW_TOTAL>>>(tok, wh + W_FF1, ff_b1, g, MTOK, 2 * INNER, CCH);
    // fused FF2 + proj_out + spatial residual:
    //   out = hs@Wp + g@Wcomb + bc + x    (split-K GEMM, K = 320 + 1280)
    bgemm_kernel<6><<<gN320, 256, SM_TOTAL>>>(hs, wh + W_POUT, g, wh + W_COMB,
        bc, out, x, nullptr, nullptr, nullptr, MTOK, CCH, CCH + INNER);
}

// round 17
// speedup vs baseline: 1.0526x; 1.0526x over previous
#include <cuda_runtime.h>
#include <cuda_fp16.h>
#include <math.h>
#include <stdint.h>

// ---------------- problem constants ----------------
#define FNUM  16
#define CCH   320
#define HWN   1024
#define BFN   32            // B*F
#define MTOK  32768         // BFN*HWN
#define NHEAD 8
#define DHEAD 40
#define NGRP  32
#define CPG   10
#define INNER 1280

// ---------------- scratch ----------------
__device__ __half g_hs [(size_t)MTOK * CCH];
__device__ __half g_q  [(size_t)MTOK * CCH];
__device__ __half g_k  [(size_t)MTOK * CCH];
__device__ __half g_v  [(size_t)MTOK * CCH];
__device__ __half g_tok[(size_t)MTOK * CCH];
__device__ __half g_o  [(size_t)MTOK * CCH];
__device__ __half g_g  [(size_t)MTOK * INNER];
#define WTOT 2252800
__device__ __half g_wh[WTOT];
__device__ float g_pe [FNUM * CCH];
__device__ float g_gnm[BFN * NGRP];
__device__ float g_gnr[BFN * NGRP];

// weight pool offsets (elements)
#define W_PIN   0
#define W_QKV0  102400
#define W_O0    409600
#define W_QKV1  512000
#define W_O1    819200
#define W_FF1   921600
#define W_FF2   1740800
#define W_POUT  2150400

// ================= helpers =================
__device__ __forceinline__ void ldsm4(uint32_t* r, const void* p) {
    uint32_t a = (uint32_t)__cvta_generic_to_shared(p);
    asm volatile("ldmatrix.sync.aligned.m8n8.x4.shared.b16 {%0,%1,%2,%3}, [%4];"
        : "=r"(r[0]), "=r"(r[1]), "=r"(r[2]), "=r"(r[3]) : "r"(a));
}
__device__ __forceinline__ void ldsm4t(uint32_t* r, const void* p) {
    uint32_t a = (uint32_t)__cvta_generic_to_shared(p);
    asm volatile("ldmatrix.sync.aligned.m8n8.x4.trans.shared.b16 {%0,%1,%2,%3}, [%4];"
        : "=r"(r[0]), "=r"(r[1]), "=r"(r[2]), "=r"(r[3]) : "r"(a));
}
__device__ __forceinline__ void mma16816(float* d, const uint32_t* a, const uint32_t* b) {
    asm volatile("mma.sync.aligned.m16n8k16.row.col.f32.f16.f16.f32 "
        "{%0,%1,%2,%3}, {%4,%5,%6,%7}, {%8,%9}, {%0,%1,%2,%3};"
        : "+f"(d[0]), "+f"(d[1]), "+f"(d[2]), "+f"(d[3])
        : "r"(a[0]), "r"(a[1]), "r"(a[2]), "r"(a[3]), "r"(b[0]), "r"(b[1]));
}
__device__ __forceinline__ void cpa16(void* dst, const void* src) {
    uint32_t d = (uint32_t)__cvta_generic_to_shared(dst);
    asm volatile("cp.async.cg.shared.global [%0], [%1], 16;" :: "r"(d), "l"(src));
}
#define CP_COMMIT() asm volatile("cp.async.commit_group;" ::: "memory")
#define CP_WAIT2()  asm volatile("cp.async.wait_group 2;" ::: "memory")

__device__ __forceinline__ uint32_t pack_h2(float t0, float t1) {
    __half h0 = __float2half_rn(t0), h1 = __float2half_rn(t1);
    return (uint32_t)__half_as_ushort(h0) | ((uint32_t)__half_as_ushort(h1) << 16);
}

// ================= single-pass fp16 GEMM, 4-stage cp.async pipeline =========
// MODE 0: Hs[m,n] = fp16(v + bias)
// MODE 1: Hs[perm(m),n] += v + bias      (fp16 RMW)
// MODE 2: out[(bf*CCH+n)*HWN+hw] = v + bias + X   (smem-transposed, coalesced)
// MODE 3: t = Hs[m,n]+v+bias; O[m,n] = fp16(t)
// MODE 4: QKV n-split -> Hs/Hk/Hv (fp16)
#define APAD 40
#define BPAD 72
#define SM_A_STG 10240            // 128 rows * 80B
#define SM_B_STG 4608             // 32 rows * 144B
#define SM_A(s) ((s) * SM_A_STG)
#define SM_B(s) (40960 + (s) * SM_B_STG)
#define SM_TOTAL 59392
#define TRP 132                   // MODE2 transpose pitch (floats)

template <int MODE>
__global__ __launch_bounds__(256, 3) void bgemm_kernel(
    const __half* __restrict__ Ag, const __half* __restrict__ Bg,
    const float* __restrict__ bias, float* __restrict__ C,
    const float* __restrict__ X,
    __half* __restrict__ Hs, __half* __restrict__ Hk, __half* __restrict__ Hv,
    __half* __restrict__ O, int M, int N, int K)
{
    extern __shared__ char sm[];
    const int tid  = threadIdx.x;
    const int lane = tid & 31;
    const int wm   = (tid >> 5) & 3;
    const int wn   = tid >> 7;
    const int m0   = blockIdx.y * 128;
    const int n0   = blockIdx.x * 64;

    const int mbase = wm * 32;
    const int nbase = wn * 32;
    const int lrow  = lane & 15;
    const int lcol8 = (lane >> 4) * 8;

    float acc[2][4][4];
    #pragma unroll
    for (int a = 0; a < 2; a++)
        #pragma unroll
        for (int b = 0; b < 4; b++)
            #pragma unroll
            for (int c = 0; c < 4; c++) acc[a][b][c] = 0.f;

    const int arow0 = tid >> 1;
    const int ac0   = (tid & 1) * 2;
    const int brow  = tid >> 3;
    const int bch   = tid & 7;

    auto load_stage = [&](int s, int kt) {
        #pragma unroll
        for (int i = 0; i < 2; i++) {
            int c = ac0 + i;
            cpa16(sm + SM_A(s) + arow0 * 80 + c * 16,
                  Ag + (size_t)(m0 + arow0) * K + kt + c * 8);
        }
        cpa16(sm + SM_B(s) + brow * 144 + bch * 16,
              Bg + (size_t)(kt + brow) * N + n0 + bch * 8);
    };

    const int ntile = K >> 5;
    load_stage(0, 0);  CP_COMMIT();
    load_stage(1, 32); CP_COMMIT();
    load_stage(2, 64); CP_COMMIT();

    for (int t = 0; t < ntile; t++) {
        CP_WAIT2();
        __syncthreads();
        if (t + 3 < ntile) load_stage((t + 3) & 3, (t + 3) * 32);
        CP_COMMIT();

        const int s = t & 3;
        const __half (*As)[APAD] = (const __half(*)[APAD])(sm + SM_A(s));
        const __half (*Bs)[BPAD] = (const __half(*)[BPAD])(sm + SM_B(s));

        #pragma unroll
        for (int ks = 0; ks < 2; ks++) {
            uint32_t ah[2][4], bh[4][2];
            #pragma unroll
            for (int mi = 0; mi < 2; mi++)
                ldsm4(ah[mi], &As[mbase + mi * 16 + lrow][ks * 16 + lcol8]);
            #pragma unroll
            for (int nj = 0; nj < 2; nj++) {
                uint32_t tmp[4];
                ldsm4t(tmp, &Bs[ks * 16 + lrow][nbase + nj * 16 + lcol8]);
                bh[nj * 2][0] = tmp[0]; bh[nj * 2][1] = tmp[1];
                bh[nj * 2 + 1][0] = tmp[2]; bh[nj * 2 + 1][1] = tmp[3];
            }
            #pragma unroll
            for (int mi = 0; mi < 2; mi++)
                #pragma unroll
                for (int ni = 0; ni < 4; ni++)
                    mma16816(acc[mi][ni], ah[mi], bh[ni]);
        }
    }

    // ---- epilogue ----
    const int erow = lane >> 2;
    const int ecol = (lane & 3) * 2;

    if (MODE == 2) {
        __syncthreads();
        float* tr = (float*)sm;   // 64 * TRP floats = 33792 B < SM_TOTAL
        #pragma unroll
        for (int mi = 0; mi < 2; mi++) {
            #pragma unroll
            for (int rr = 0; rr < 2; rr++) {
                const int ml = mbase + mi * 16 + rr * 8 + erow;
                #pragma unroll
                for (int ni = 0; ni < 4; ni++) {
                    const int nl = nbase + ni * 8 + ecol;
                    tr[nl * TRP + ml]       = acc[mi][ni][rr * 2 + 0] + bias[n0 + nl];
                    tr[(nl + 1) * TRP + ml] = acc[mi][ni][rr * 2 + 1] + bias[n0 + nl + 1];
                }
            }
        }
        __syncthreads();
        const int bfi = m0 >> 10, hw0 = m0 & 1023;
        const int warp = tid >> 5;
        #pragma unroll
        for (int r8 = 0; r8 < 8; r8++) {
            const int n = warp + r8 * 8;
            size_t off = ((size_t)(bfi * CCH + n0 + n)) * HWN + hw0 + lane * 4;
            float4 xv = *(const float4*)(X + off);
            const float* tp = tr + n * TRP + lane * 4;
            float4 w;
            w.x = tp[0] + xv.x;
            w.y = tp[1] + xv.y;
            w.z = tp[2] + xv.z;
            w.w = tp[3] + xv.w;
            *(float4*)(C + off) = w;
        }
        return;
    }

    const int seg4 = (n0 + nbase) / CCH;   // MODE 4: constant per warp
    #pragma unroll
    for (int mi = 0; mi < 2; mi++) {
        #pragma unroll
        for (int rr = 0; rr < 2; rr++) {
            const int m = m0 + mbase + mi * 16 + rr * 8 + erow;
            int mrow = m;
            if (MODE == 1) {
                int f = m & 15, nd = m >> 4;
                mrow = (((nd >> 10) * FNUM + f) << 10) + (nd & 1023);
            }
            #pragma unroll
            for (int ni = 0; ni < 4; ni++) {
                const int n = n0 + nbase + ni * 8 + ecol;
                float v0 = acc[mi][ni][rr * 2 + 0];
                float v1 = acc[mi][ni][rr * 2 + 1];
                if (bias) { v0 += bias[n]; v1 += bias[n + 1]; }
                if (MODE == 0) {
                    *(uint32_t*)(Hs + (size_t)mrow * N + n) = pack_h2(v0, v1);
                } else if (MODE == 1) {
                    uint32_t* p = (uint32_t*)(Hs + (size_t)mrow * N + n);
                    float2 old = __half22float2(*(const __half2*)p);
                    *p = pack_h2(old.x + v0, old.y + v1);
                } else if (MODE == 3) {
                    size_t off = (size_t)mrow * N + n;
                    float2 old = __half22float2(*(const __half2*)(Hs + off));
                    *(uint32_t*)(O + off) = pack_h2(old.x + v0, old.y + v1);
                } else { // MODE 4
                    __half* dst = (seg4 == 0) ? Hs : (seg4 == 1) ? Hk : Hv;
                    *(uint32_t*)(dst + (size_t)m * CCH + (n - seg4 * CCH)) = pack_h2(v0, v1);
                }
            }
        }
    }
}

// ================= FF1+GEGLU: 128x128 tile, 4-stage, interleaved weights ====
#define BW_PITCH 136              // halves per B row (272 B)
#define SMW_A_STG 10240
#define SMW_B_STG 8704            // 32 * 272B
#define SMW_A(s) ((s) * SMW_A_STG)
#define SMW_B(s) (40960 + (s) * SMW_B_STG)
#define SMW_TOTAL 75776

__global__ __launch_bounds__(256, 2) void ff1_kernel(
    const __half* __restrict__ Ag, const __half* __restrict__ Bg,
    const float* __restrict__ bias, __half* __restrict__ O, int M, int N, int K)
{
    extern __shared__ char sm[];
    const int tid  = threadIdx.x;
    const int lane = tid & 31;
    const int wm   = (tid >> 5) & 3;
    const int wn   = tid >> 7;
    const int m0   = blockIdx.y * 128;
    const int n0   = blockIdx.x * 128;

    const int mbase = wm * 32;
    const int nbase = wn * 64;
    const int lrow  = lane & 15;
    const int lcol8 = (lane >> 4) * 8;

    float acc[2][8][4];
    #pragma unroll
    for (int a = 0; a < 2; a++)
        #pragma unroll
        for (int b = 0; b < 8; b++)
            #pragma unroll
            for (int c = 0; c < 4; c++) acc[a][b][c] = 0.f;

    const int arow0 = tid >> 1;
    const int ac0   = (tid & 1) * 2;
    const int brow  = tid >> 3;
    const int bch   = tid & 7;

    auto load_stage = [&](int s, int kt) {
        #pragma unroll
        for (int i = 0; i < 2; i++) {
            int c = ac0 + i;
            cpa16(sm + SMW_A(s) + arow0 * 80 + c * 16,
                  Ag + (size_t)(m0 + arow0) * K + kt + c * 8);
        }
        #pragma unroll
        for (int i = 0; i < 2; i++) {
            cpa16(sm + SMW_B(s) + brow * 272 + (bch + i * 8) * 16,
                  Bg + (size_t)(kt + brow) * N + n0 + bch * 8 + i * 64);
        }
    };

    const int ntile = K >> 5;
    load_stage(0, 0);  CP_COMMIT();
    load_stage(1, 32); CP_COMMIT();
    load_stage(2, 64); CP_COMMIT();

    for (int t = 0; t < ntile; t++) {
        CP_WAIT2();
        __syncthreads();
        if (t + 3 < ntile) load_stage((t + 3) & 3, (t + 3) * 32);
        CP_COMMIT();

        const int s = t & 3;
        const __half (*As)[APAD] = (const __half(*)[APAD])(sm + SMW_A(s));
        const __half (*Bs)[BW_PITCH] = (const __half(*)[BW_PITCH])(sm + SMW_B(s));

        #pragma unroll
        for (int ks = 0; ks < 2; ks++) {
            uint32_t ah[2][4], bh[8][2];
            #pragma unroll
            for (int mi = 0; mi < 2; mi++)
                ldsm4(ah[mi], &As[mbase + mi * 16 + lrow][ks * 16 + lcol8]);
            #pragma unroll
            for (int nj = 0; nj < 4; nj++) {
                uint32_t tmp[4];
                ldsm4t(tmp, &Bs[ks * 16 + lrow][nbase + nj * 16 + lcol8]);
                bh[nj * 2][0] = tmp[0]; bh[nj * 2][1] = tmp[1];
                bh[nj * 2 + 1][0] = tmp[2]; bh[nj * 2 + 1][1] = tmp[3];
            }
            #pragma unroll
            for (int mi = 0; mi < 2; mi++)
                #pragma unroll
                for (int ni = 0; ni < 8; ni++)
                    mma16816(acc[mi][ni], ah[mi], bh[ni]);
        }
    }

    // ---- epilogue: GEGLU on interleaved (a,g) 16-col pairs ----
    const int erow = lane >> 2;
    const int ecol = (lane & 3) * 2;
    #pragma unroll
    for (int mi = 0; mi < 2; mi++) {
        #pragma unroll
        for (int rr = 0; rr < 2; rr++) {
            const int m = m0 + mbase + mi * 16 + rr * 8 + erow;
            #pragma unroll
            for (int p = 0; p < 4; p++) {
                const int tile16 = (n0 + nbase + p * 16) >> 4;
                const int acol = tile16 * 8 + ecol;
                float a0 = acc[mi][2 * p][rr * 2 + 0] + bias[acol];
                float a1 = acc[mi][2 * p][rr * 2 + 1] + bias[acol + 1];
                float g0 = acc[mi][2 * p + 1][rr * 2 + 0] + bias[INNER + acol];
                float g1 = acc[mi][2 * p + 1][rr * 2 + 1] + bias[INNER + acol + 1];
                float r0 = a0 * (0.5f * g0 * (1.f + erff(g0 * 0.7071067811865476f)));
                float r1 = a1 * (0.5f * g1 * (1.f + erff(g1 * 0.7071067811865476f)));
                *(uint32_t*)(O + (size_t)m * INNER + acol) = pack_h2(r0, r1);
            }
        }
    }
}

// ---------------- fused prologue: weight conv + GN stats + PE ---------------
struct WSegs {
    const float* src[12];
    int off[12], rows[12], cols[12], pitch[12], coloff[12], ilv[12], blk0[12];
    int cwBlocks;   // convw block count; gn_stats occupies [cw, cw+1024), pe [cw+1024, cw+1040)
};
__global__ __launch_bounds__(256) void prologue_kernel(
    WSegs T, __half* __restrict__ dh,
    const float* __restrict__ x, float* __restrict__ mean, float* __restrict__ rstd,
    float* __restrict__ pe)
{
    __shared__ float ss[8], qq[8];
    int b = blockIdx.x;
    if (b < T.cwBlocks) {
        int s = 0;
        #pragma unroll
        for (int i = 1; i < 12; i++) if (b >= T.blk0[i]) s = i;
        int idx = (b - T.blk0[s]) * 256 + threadIdx.x;
        int cols = T.cols[s];
        if (idx >= T.rows[s] * cols) return;
        int r = idx / cols, c = idx % cols;
        float v = T.src[s][idx];
        int nc;
        if (T.ilv[s]) {
            int half = cols >> 1;
            if (c < half) nc = (c >> 3) * 16 + (c & 7);
            else { int c2 = c - half; nc = (c2 >> 3) * 16 + 8 + (c2 & 7); }
        } else {
            nc = T.coloff[s] + c;
        }
        dh[(size_t)T.off[s] + (size_t)r * T.pitch[s] + nc] = __float2half_rn(v);
    } else if (b < T.cwBlocks + BFN * NGRP) {
        int bg = b - T.cwBlocks;
        int bf = bg >> 5, g = bg & 31;
        const float* p = x + ((size_t)bf * CCH + g * CPG) * HWN;
        float s = 0.f, q = 0.f;
        for (int idx = threadIdx.x; idx < CPG * HWN; idx += 256) {
            float v = p[idx];
            s += v; q += v * v;
        }
        #pragma unroll
        for (int o = 16; o > 0; o >>= 1) {
            s += __shfl_xor_sync(0xffffffffu, s, o);
            q += __shfl_xor_sync(0xffffffffu, q, o);
        }
        int warp = threadIdx.x >> 5, lane = threadIdx.x & 31;
        if (lane == 0) { ss[warp] = s; qq[warp] = q; }
        __syncthreads();
        if (threadIdx.x == 0) {
            float S = 0.f, Q = 0.f;
            #pragma unroll
            for (int i = 0; i < 8; i++) { S += ss[i]; Q += qq[i]; }
            float m = S / (float)(CPG * HWN);
            float var = Q / (float)(CPG * HWN) - m * m;
            mean[bg] = m;
            rstd[bg] = rsqrtf(var + 1e-6f);
        }
    } else {
        int p = b - T.cwBlocks - BFN * NGRP;   // 0..15
        int i = threadIdx.x;
        if (i < CCH / 2) {
            double div = exp((double)(2 * i) * (-log(10000.0) / (double)CCH));
            double a = (double)p * div;
            pe[p * CCH + 2 * i]     = (float)sin(a);
            pe[p * CCH + 2 * i + 1] = (float)cos(a);
        }
    }
}

// ---------------- GroupNorm apply + transpose -> fp16 tokens ----------------
__global__ void gn_tok_kernel(
    const float* __restrict__ x, const float* __restrict__ gw, const float* __restrict__ gb,
    const float* __restrict__ mean, const float* __restrict__ rstd,
    __half* __restrict__ th)
{
    __shared__ float tile[32][33];
    int bf = blockIdx.z;
    int c0 = blockIdx.y * 32;
    int hw0 = blockIdx.x * 32;
    #pragma unroll
    for (int j = 0; j < 4; j++) {
        int c = c0 + threadIdx.y + j * 8;
        float v = x[((size_t)bf * CCH + c) * HWN + hw0 + threadIdx.x];
        int bg = bf * NGRP + c / CPG;
        v = (v - mean[bg]) * rstd[bg] * gw[c] + gb[c];
        tile[threadIdx.y + j * 8][threadIdx.x] = v;
    }
    __syncthreads();
    #pragma unroll
    for (int j = 0; j < 4; j++) {
        int hw = hw0 + threadIdx.y + j * 8;
        float v = tile[threadIdx.x][threadIdx.y + j * 8];
        th[((size_t)bf * HWN + hw) * CCH + c0 + threadIdx.x] = __float2half_rn(v);
    }
}

// ---------------- LayerNorm (warp per row, fp16 in/out) ----------------
__global__ __launch_bounds__(256) void ln_kernel(
    const __half* __restrict__ in, const float* __restrict__ w, const float* __restrict__ bvec,
    const float* __restrict__ pe, __half* __restrict__ oh, int temporal)
{
    const int warp = threadIdx.x >> 5, lane = threadIdx.x & 31;
    const int r = blockIdx.x * 8 + warp;
    int src = r, f = 0;
    if (temporal) {
        f = r & 15;
        int nd = r >> 4;
        src = (((nd >> 10) * FNUM + f) << 10) + (nd & 1023);
    }
    const __half2* row2 = (const __half2*)(in + (size_t)src * CCH);
    float2 vv[5];
    float s = 0.f, q = 0.f;
    #pragma unroll
    for (int i = 0; i < 5; i++) {
        float2 v = __half22float2(row2[lane + i * 32]);
        vv[i] = v;
        s += v.x + v.y;
        q += v.x * v.x + v.y * v.y;
    }
    #pragma unroll
    for (int o = 16; o > 0; o >>= 1) {
        s += __shfl_xor_sync(0xffffffffu, s, o);
        q += __shfl_xor_sync(0xffffffffu, q, o);
    }
    const float m = s / (float)CCH;
    const float rs = rsqrtf(q / (float)CCH - m * m + 1e-5f);
    uint32_t* orow = (uint32_t*)(oh + (size_t)r * CCH);
    #pragma unroll
    for (int i = 0; i < 5; i++) {
        int c = (lane + i * 32) * 2;
        float o0 = (vv[i].x - m) * rs * w[c] + bvec[c];
        float o1 = (vv[i].y - m) * rs * w[c + 1] + bvec[c + 1];
        if (temporal) { o0 += pe[f * CCH + c]; o1 += pe[f * CCH + c + 1]; }
        orow[lane + i * 32] = pack_h2(o0, o1);
    }
}

// ---------------- temporal attention (fp16 smem staging, pitch 322) --------
#define ATP 322                   // halves per staged row (644 B ≡ 1 bank stride)
#define ATT_SMEM (3 * 16 * ATP * 2 + 8 * 16 * 16 * 4)
__global__ __launch_bounds__(256) void attn_kernel(
    const __half* __restrict__ Q, const __half* __restrict__ K,
    const __half* __restrict__ V, __half* __restrict__ Oh)
{
    extern __shared__ char smb[];
    __half* qh = (__half*)smb;
    __half* kh = qh + 16 * ATP;
    __half* vh = kh + 16 * ATP;
    float* sc  = (float*)(smb + 3 * 16 * ATP * 2);   // [8][16][16]
    const int tid = threadIdx.x;
    const size_t base = (size_t)blockIdx.x * FNUM * CCH;

    #pragma unroll
    for (int i = 0; i < 10; i++) {
        int idx2 = tid + i * 256;           // 2560 half2 per matrix
        int row = idx2 / 160;
        int c2 = (idx2 % 160) * 2;
        *(__half2*)(qh + row * ATP + c2) = *(const __half2*)(Q + base + row * CCH + c2);
        *(__half2*)(kh + row * ATP + c2) = *(const __half2*)(K + base + row * CCH + c2);
        *(__half2*)(vh + row * ATP + c2) = *(const __half2*)(V + base + row * CCH + c2);
    }
    __syncthreads();

    {
        const int qf = tid >> 4, kf = tid & 15;
        const __half* qp = qh + qf * ATP;
        const __half* kp = kh + kf * ATP;
        #pragma unroll
        for (int h = 0; h < 8; h++) {
            float s = 0.f;
            #pragma unroll
            for (int j2 = 0; j2 < DHEAD / 2; j2++) {
                float2 a = __half22float2(*(const __half2*)(qp + h * DHEAD + j2 * 2));
                float2 b = __half22float2(*(const __half2*)(kp + h * DHEAD + j2 * 2));
                s = fmaf(a.x, b.x, s);
                s = fmaf(a.y, b.y, s);
            }
            sc[h * 256 + qf * 16 + kf] = s * 0.15811388300841897f;
        }
    }
    __syncthreads();

    if (tid < 128) {
        float* row = sc + (tid >> 4) * 256 + (tid & 15) * 16;
        float m = -1e30f;
        #pragma unroll
        for (int k2 = 0; k2 < 16; k2++) m = fmaxf(m, row[k2]);
        float sum = 0.f;
        #pragma unroll
        for (int k2 = 0; k2 < 16; k2++) {
            float e = expf(row[k2] - m);
            row[k2] = e;
            sum += e;
        }
        float inv = 1.f / sum;
        #pragma unroll
        for (int k2 = 0; k2 < 16; k2++) row[k2] *= inv;
    }
    __syncthreads();

    #pragma unroll
    for (int i = 0; i < 20; i++) {
        int idx = tid + i * 256;
        int f = idx / CCH, c = idx % CCH;
        int h = c / DHEAD;
        const float* pr = sc + h * 256 + f * 16;
        float o = 0.f;
        #pragma unroll
        for (int k2 = 0; k2 < 16; k2++)
            o = fmaf(pr[k2], __half2float(vh[k2 * ATP + c]), o);
        Oh[base + (size_t)f * CCH + c] = __float2half_rn(o);
    }
}

// ---------------- host orchestration ----------------
extern "C" void kernel_launch(void* const* d_in, const int* in_sizes, int n_in,
                              void* d_out, int out_size)
{
    const float* x      = (const float*)d_in[0];
    const float* gn_w   = (const float*)d_in[1];
    const float* gn_b   = (const float*)d_in[2];
    const float* pin_w  = (const float*)d_in[3];
    const float* pin_b  = (const float*)d_in[4];
    const float* lnw[2]  = { (const float*)d_in[5],  (const float*)d_in[12] };
    const float* lnb[2]  = { (const float*)d_in[6],  (const float*)d_in[13] };
    const float* wq[2]   = { (const float*)d_in[7],  (const float*)d_in[14] };
    const float* wk[2]   = { (const float*)d_in[8],  (const float*)d_in[15] };
    const float* wv[2]   = { (const float*)d_in[9],  (const float*)d_in[16] };
    const float* wo[2]   = { (const float*)d_in[10], (const float*)d_in[17] };
    const float* bo[2]   = { (const float*)d_in[11], (const float*)d_in[18] };
    const float* ffln_w = (const float*)d_in[19];
    const float* ffln_b = (const float*)d_in[20];
    const float* ff_w1  = (const float*)d_in[21];
    const float* ff_b1  = (const float*)d_in[22];
    const float* ff_w2  = (const float*)d_in[23];
    const float* ff_b2  = (const float*)d_in[24];
    const float* pout_w = (const float*)d_in[25];
    const float* pout_b = (const float*)d_in[26];
    float* out = (float*)d_out;

    float *pe, *gnm, *gnr;
    __half *hs, *q, *k, *v, *tok, *o, *g, *wh;
    cudaGetSymbolAddress((void**)&hs,  g_hs);
    cudaGetSymbolAddress((void**)&q,   g_q);
    cudaGetSymbolAddress((void**)&k,   g_k);
    cudaGetSymbolAddress((void**)&v,   g_v);
    cudaGetSymbolAddress((void**)&pe,  g_pe);
    cudaGetSymbolAddress((void**)&gnm, g_gnm);
    cudaGetSymbolAddress((void**)&gnr, g_gnr);
    cudaGetSymbolAddress((void**)&tok, g_tok);
    cudaGetSymbolAddress((void**)&o,   g_o);
    cudaGetSymbolAddress((void**)&g,   g_g);
    cudaGetSymbolAddress((void**)&wh,  g_wh);

    cudaFuncSetAttribute(bgemm_kernel<0>, cudaFuncAttributeMaxDynamicSharedMemorySize, SM_TOTAL);
    cudaFuncSetAttribute(bgemm_kernel<1>, cudaFuncAttributeMaxDynamicSharedMemorySize, SM_TOTAL);
    cudaFuncSetAttribute(bgemm_kernel<2>, cudaFuncAttributeMaxDynamicSharedMemorySize, SM_TOTAL);
    cudaFuncSetAttribute(bgemm_kernel<3>, cudaFuncAttributeMaxDynamicSharedMemorySize, SM_TOTAL);
    cudaFuncSetAttribute(bgemm_kernel<4>, cudaFuncAttributeMaxDynamicSharedMemorySize, SM_TOTAL);
    cudaFuncSetAttribute(ff1_kernel, cudaFuncAttributeMaxDynamicSharedMemorySize, SMW_TOTAL);
    cudaFuncSetAttribute(attn_kernel, cudaFuncAttributeMaxDynamicSharedMemorySize, ATT_SMEM);

    dim3 gN320(5, 256);
    dim3 gQKV(15, 256);
    dim3 gFF1(20, 256);

    // fused prologue: weight conversion + GN stats + PE in ONE launch
    {
        WSegs T;
        const float* srcs[12] = { pin_w, wq[0], wk[0], wv[0], wo[0],
                                  wq[1], wk[1], wv[1], wo[1], ff_w1, ff_w2, pout_w };
        int offs[12]  = { W_PIN, W_QKV0, W_QKV0, W_QKV0, W_O0,
                          W_QKV1, W_QKV1, W_QKV1, W_O1, W_FF1, W_FF2, W_POUT };
        int rows[12]  = { 320, 320, 320, 320, 320, 320, 320, 320, 320, 320, 1280, 320 };
        int cols[12]  = { 320, 320, 320, 320, 320, 320, 320, 320, 320, 2560, 320, 320 };
        int pitch[12] = { 320, 960, 960, 960, 320, 960, 960, 960, 320, 2560, 320, 320 };
        int colo[12]  = { 0, 0, 320, 640, 0, 0, 320, 640, 0, 0, 0, 0 };
        int ilv[12]   = { 0, 0, 0, 0, 0, 0, 0, 0, 0, 1, 0, 0 };
        int blk = 0;
        for (int i = 0; i < 12; i++) {
            T.src[i] = srcs[i]; T.off[i] = offs[i]; T.rows[i] = rows[i]; T.cols[i] = cols[i];
            T.pitch[i] = pitch[i]; T.coloff[i] = colo[i]; T.ilv[i] = ilv[i];
            T.blk0[i] = blk;
            blk += (rows[i] * cols[i] + 255) / 256;
        }
        T.cwBlocks = blk;
        prologue_kernel<<<blk + BFN * NGRP + FNUM, 256>>>(T, wh, x, gnm, gnr, pe);
    }
    gn_tok_kernel<<<dim3(HWN / 32, CCH / 32, BFN), dim3(32, 8)>>>(x, gn_w, gn_b, gnm, gnr, tok);

    // proj_in -> hs (fp16)
    bgemm_kernel<0><<<gN320, 256, SM_TOTAL>>>(tok, wh + W_PIN,
        pin_b, nullptr, nullptr, hs, nullptr, nullptr, nullptr, MTOK, CCH, CCH);

    const int WQKV[2] = { W_QKV0, W_QKV1 };
    const int WO[2]   = { W_O0, W_O1 };
    for (int i = 0; i < 2; i++) {
        ln_kernel<<<MTOK / 8, 256>>>(hs, lnw[i], lnb[i], pe, tok, 1);
        bgemm_kernel<4><<<gQKV, 256, SM_TOTAL>>>(tok, wh + WQKV[i],
            nullptr, nullptr, nullptr, q, k, v, nullptr, MTOK, 960, CCH);
        attn_kernel<<<2048, 256, ATT_SMEM>>>(q, k, v, o);
        bgemm_kernel<1><<<gN320, 256, SM_TOTAL>>>(o, wh + WO[i],
            bo[i], nullptr, nullptr, hs, nullptr, nullptr, nullptr, MTOK, CCH, CCH);
    }

    ln_kernel<<<MTOK / 8, 256>>>(hs, ffln_w, ffln_b, pe, tok, 0);
    // FF1 + GEGLU fused (interleaved weights, 128x128 tiles) -> g
    ff1_kernel<<<gFF1, 256, SMW_TOTAL>>>(tok, wh + W_FF1, ff_b1, g, MTOK, 2 * INNER, CCH);
    // FF down-proj + residual (hs read) -> tok (fp16)
    bgemm_kernel<3><<<gN320, 256, SM_TOTAL>>>(g, wh + W_FF2,
        ff_b2, nullptr, nullptr, hs, nullptr, nullptr, tok, MTOK, CCH, INNER);
    // proj_out + spatial residual (smem-transposed coalesced epilogue)
    bgemm_kernel<2><<<gN320, 256, SM_TOTAL>>>(tok, wh + W_POUT,
        pout_b, out, x, nullptr, nullptr, nullptr, nullptr, MTOK, CCH, CCH);
}